// round 11
// baseline (speedup 1.0000x reference)
#include <cuda_runtime.h>
#include <cuda_bf16.h>
#include <cstdint>

// Problem constants
#define HW_     16384            // H*W = 128*128
#define CHW_    4194304          // C*H*W = 256*16384
#define NB_     8                // batch
#define JD_     32768            // C*H*W / W = 32768 (reshaped inner dim)
#define SPLITK_ 128              // split-K factor for logit GEMM
#define KCH_    256              // 32768 / 128

// Output chunk offsets (floats) for the concatenated tuple
// (out_w, x_Qw, x_Kw, x_Vw, gamma, att)
#define OFF_OUTW  0
#define OFF_QW    33554432
#define OFF_KW    67108864
#define OFF_VW    100663296
#define OFF_GAMMA 134217728
#define OFF_ATT   134217729
#define FULL_SIZE 134348801

// ---------------- device-global scratch (no allocations allowed) -----------
__device__ float g_kscr[(size_t)NB_ * CHW_];             // K conv, normal layout
__device__ float g_vscr[(size_t)NB_ * CHW_];             // V conv, normal layout
__device__ float g_psum[(size_t)NB_ * SPLITK_ * 16384];  // split-K partial logits
__device__ float g_att [(size_t)NB_ * 16384];            // softmax result
__device__ uint32_t g_whi[3 * 256 * 128];                // W hi bf16x2 [op][m][k/2]
__device__ uint32_t g_wlo[3 * 256 * 128];                // W lo bf16x2
// fallback buffers in case d_out only holds out_w
__device__ float g_qfb [(size_t)NB_ * CHW_];
__device__ float g_ktfb[(size_t)NB_ * CHW_];
__device__ float g_vtfb[(size_t)NB_ * CHW_];

// ---------------- bf16 hi/lo split helpers ---------------------------------
__device__ __forceinline__ void split2(float x, float y, uint32_t& hi, uint32_t& lo) {
    __nv_bfloat16 hx = __float2bfloat16_rn(x);
    __nv_bfloat16 hy = __float2bfloat16_rn(y);
    __nv_bfloat162 h; h.x = hx; h.y = hy;                    // .x = low 16 bits
    hi = *reinterpret_cast<uint32_t*>(&h);
    __nv_bfloat162 l = __floats2bfloat162_rn(x - __bfloat162float(hx),
                                             y - __bfloat162float(hy));
    lo = *reinterpret_cast<uint32_t*>(&l);
}

// mma.sync m16n8k16 bf16 (baseline PTX, sm_80+) — fp32 accumulate in-place
__device__ __forceinline__ void mma16816(float* c, const uint32_t a[4],
                                         uint32_t b0, uint32_t b1) {
    asm("mma.sync.aligned.m16n8k16.row.col.f32.bf16.bf16.f32 "
        "{%0,%1,%2,%3}, {%4,%5,%6,%7}, {%8,%9}, {%0,%1,%2,%3};"
        : "+f"(c[0]), "+f"(c[1]), "+f"(c[2]), "+f"(c[3])
        : "r"(a[0]), "r"(a[1]), "r"(a[2]), "r"(a[3]), "r"(b0), "r"(b1));
}

#define HACC_INIT(acc)                                         \
    float acc[2][8][4];                                        \
    _Pragma("unroll")                                          \
    for (int _i = 0; _i < 2; _i++)                             \
        _Pragma("unroll")                                      \
        for (int _j = 0; _j < 8; _j++)                         \
            _Pragma("unroll")                                  \
            for (int _e = 0; _e < 4; _e++) acc[_i][_j][_e] = 0.f;

// ---------------- W pre-split kernel ----------------------------------------
// g_whi/g_wlo[op][m][j]: u32 j holds bf16 pair (k=2j low half, k=2j+1 high).
__global__ void wsplit_kernel(const float* __restrict__ Wq,
                              const float* __restrict__ Wk,
                              const float* __restrict__ Wv)
{
    const int idx = blockIdx.x * 256 + threadIdx.x;   // 3*256*128 = 98304
    const int op  = idx >> 15;
    const int rem = idx & 32767;
    const float* W = (op == 0) ? Wq : (op == 1) ? Wk : Wv;
    float2 v = *(const float2*)(W + (size_t)rem * 2);
    uint32_t hi, lo;
    split2(v.x, v.y, hi, lo);
    g_whi[idx] = hi;
    g_wlo[idx] = lo;
}

// ---------------- 3-pass HMMA GEMM core (att / out) -------------------------
// C[128,128] = A[128,K] * B[K,128]; A row-major (lda), B k-major (ldb).
// Double-buffered smem: per buffer Ah@0 Al@1536 Bh@3072 Bl@4608 (u32),
// row stride 12 (16 bf16/row); buffers at sm and sm+6144.
// 8 warps 4(m)x2(n), warp 32x64. ONE __syncthreads per chunk:
//   stage(ch)->buf[ch&1]; prefetch(ch+1); sync; frag+MMA from buf[ch&1].
// Cross-warp, stage(ch+1) overlaps other warps' MMA(ch) — different buffers.
__device__ __forceinline__ void hmma_gemm128(
    const float* __restrict__ Ag, int lda,
    const float* __restrict__ Bg, int ldb,
    int nChunks, float acc[2][8][4], uint32_t* sm)
{
    const int tid  = threadIdx.x;
    const int lane = tid & 31;
    const int w    = tid >> 5;
    const int g    = lane >> 2;
    const int t4   = lane & 3;
    const int wm   = w & 3;
    const int wn   = w >> 2;

    const int saRow = tid >> 1;
    const int saSeg = (tid & 1) << 3;
    const int sbKp  = tid >> 5;
    const int sbNq  = tid & 31;

    const float* aP = Ag + (size_t)saRow * lda + saSeg;
    const float* bP = Bg + (size_t)(2 * sbKp) * ldb + sbNq * 4;

    float4 fa0 = *(const float4*)aP;
    float4 fa1 = *(const float4*)(aP + 4);
    float4 fb0 = *(const float4*)bP;
    float4 fb1 = *(const float4*)(bP + ldb);

    #pragma unroll 1
    for (int ch = 0; ch < nChunks; ch++) {
        uint32_t* buf = sm + (ch & 1) * 6144;

        // ---- stage chunk ch from regs into buf (hi/lo split) --------------
        {
            uint32_t h0, l0, h1, l1, h2, l2, h3, l3;
            split2(fa0.x, fa0.y, h0, l0);
            split2(fa0.z, fa0.w, h1, l1);
            split2(fa1.x, fa1.y, h2, l2);
            split2(fa1.z, fa1.w, h3, l3);
            uint32_t base = saRow * 12 + (saSeg >> 1);
            buf[base + 0] = h0; buf[base + 1] = h1;
            buf[base + 2] = h2; buf[base + 3] = h3;
            buf[1536 + base + 0] = l0; buf[1536 + base + 1] = l1;
            buf[1536 + base + 2] = l2; buf[1536 + base + 3] = l3;
        }
        #pragma unroll
        for (int e = 0; e < 4; e++) {
            float av = (&fb0.x)[e], cv = (&fb1.x)[e];
            uint32_t hp, lp;
            split2(av, cv, hp, lp);
            const int n = sbNq * 4 + e;
            buf[3072 + n * 12 + sbKp] = hp;
            buf[4608 + n * 12 + sbKp] = lp;
        }

        // ---- prefetch chunk ch+1 into registers ---------------------------
        if (ch + 1 < nChunks) {
            const float* aN = aP + (ch + 1) * 16;
            const float* bN = bP + (size_t)((ch + 1) * 16) * ldb;
            fa0 = *(const float4*)aN;
            fa1 = *(const float4*)(aN + 4);
            fb0 = *(const float4*)bN;
            fb1 = *(const float4*)(bN + ldb);
        }

        __syncthreads();

        // ---- fragments + MMAs from buf ------------------------------------
        uint32_t aH[2][4], aL[2][4];
        #pragma unroll
        for (int im = 0; im < 2; im++) {
            const int rb = wm * 32 + im * 16;
            aH[im][0] = buf[(rb + g    ) * 12 + t4];
            aH[im][1] = buf[(rb + g + 8) * 12 + t4];
            aH[im][2] = buf[(rb + g    ) * 12 + 4 + t4];
            aH[im][3] = buf[(rb + g + 8) * 12 + 4 + t4];
            aL[im][0] = buf[1536 + (rb + g    ) * 12 + t4];
            aL[im][1] = buf[1536 + (rb + g + 8) * 12 + t4];
            aL[im][2] = buf[1536 + (rb + g    ) * 12 + 4 + t4];
            aL[im][3] = buf[1536 + (rb + g + 8) * 12 + 4 + t4];
        }
        #pragma unroll
        for (int jn = 0; jn < 8; jn++) {
            const int ncol = wn * 64 + jn * 8 + g;
            uint32_t bH0 = buf[3072 + ncol * 12 + t4];
            uint32_t bH1 = buf[3072 + ncol * 12 + 4 + t4];
            uint32_t bL0 = buf[4608 + ncol * 12 + t4];
            uint32_t bL1 = buf[4608 + ncol * 12 + 4 + t4];
            #pragma unroll
            for (int im = 0; im < 2; im++) {
                mma16816(acc[im][jn], aH[im], bH0, bH1);
                mma16816(acc[im][jn], aL[im], bH0, bH1);
                mma16816(acc[im][jn], aH[im], bL0, bL1);
            }
        }
    }
}

// ---------------- kernel 1: fused QKV 1x1 conv + bias + ReLU ---------------
// grid (128, 6, 8): x = n-tile, y = (m-half | op*2), z = batch  (R7 order)
// A staged from pre-split global bf16 hi/lo planes (pure u32 copies);
// B (x) staged hi/lo via split2. 3 MMA passes. Double-buffered, 1 sync/chunk.
__global__ __launch_bounds__(256, 2) void conv_qkv_kernel(
    const float* __restrict__ x,
    const float* __restrict__ bq, const float* __restrict__ bk,
    const float* __restrict__ bv,
    float* __restrict__ qdst)
{
    __shared__ uint32_t sm[12288];
    if (!qdst) qdst = g_qfb;

    const int tid  = threadIdx.x;
    const int lane = tid & 31;
    const int w    = tid >> 5;
    const int g    = lane >> 2;
    const int t4   = lane & 3;
    const int wm   = w & 3;
    const int wn   = w >> 2;

    const int b  = blockIdx.z;
    const int op = blockIdx.y >> 1;
    const int m0 = (blockIdx.y & 1) << 7;
    const int n0 = blockIdx.x << 7;

    const float* bsel = (op == 0) ? bq : (op == 1) ? bk : bv;
    float*       dst  = ((op == 0) ? qdst : (op == 1) ? g_kscr : g_vscr)
                      + (size_t)b * CHW_;
    const uint32_t* whi = g_whi + op * 32768 + m0 * 128;
    const uint32_t* wlo = g_wlo + op * 32768 + m0 * 128;
    const float* Xb = x + (size_t)b * CHW_ + n0;

    const int saRow  = tid >> 1;          // 0..127
    const int saHalf = (tid & 1) << 2;    // u32 offset 0 or 4
    const int sbKp   = tid >> 5;          // 0..7
    const int sbNq   = tid & 31;          // 0..31

    uint4 wh = *(const uint4*)(whi + saRow * 128 + saHalf);
    uint4 wl = *(const uint4*)(wlo + saRow * 128 + saHalf);
    const float* bP = Xb + (size_t)(2 * sbKp) * HW_ + sbNq * 4;
    float4 fb0 = *(const float4*)bP;
    float4 fb1 = *(const float4*)(bP + HW_);

    HACC_INIT(acc);

    #pragma unroll 1
    for (int ch = 0; ch < 16; ch++) {
        uint32_t* buf = sm + (ch & 1) * 6144;

        // ---- stage A (u32 copies) and B (hi/lo split) ---------------------
        const uint32_t abase = saRow * 12 + saHalf;
        *(uint4*)(buf + abase)        = wh;
        *(uint4*)(buf + 1536 + abase) = wl;
        #pragma unroll
        for (int e = 0; e < 4; e++) {
            float av = (&fb0.x)[e], cv = (&fb1.x)[e];
            uint32_t hp, lp;
            split2(av, cv, hp, lp);
            const int n = sbNq * 4 + e;
            buf[3072 + n * 12 + sbKp] = hp;
            buf[4608 + n * 12 + sbKp] = lp;
        }

        // ---- prefetch next chunk ------------------------------------------
        if (ch < 15) {
            wh = *(const uint4*)(whi + saRow * 128 + (ch + 1) * 8 + saHalf);
            wl = *(const uint4*)(wlo + saRow * 128 + (ch + 1) * 8 + saHalf);
            const float* bN = Xb + (size_t)((ch + 1) * 16 + 2 * sbKp) * HW_ + sbNq * 4;
            fb0 = *(const float4*)bN;
            fb1 = *(const float4*)(bN + HW_);
        }

        __syncthreads();

        // ---- fragments + MMAs ---------------------------------------------
        uint32_t aH[2][4], aL[2][4];
        #pragma unroll
        for (int im = 0; im < 2; im++) {
            const int rb = wm * 32 + im * 16;
            aH[im][0] = buf[(rb + g    ) * 12 + t4];
            aH[im][1] = buf[(rb + g + 8) * 12 + t4];
            aH[im][2] = buf[(rb + g    ) * 12 + 4 + t4];
            aH[im][3] = buf[(rb + g + 8) * 12 + 4 + t4];
            aL[im][0] = buf[1536 + (rb + g    ) * 12 + t4];
            aL[im][1] = buf[1536 + (rb + g + 8) * 12 + t4];
            aL[im][2] = buf[1536 + (rb + g    ) * 12 + 4 + t4];
            aL[im][3] = buf[1536 + (rb + g + 8) * 12 + 4 + t4];
        }
        #pragma unroll
        for (int jn = 0; jn < 8; jn++) {
            const int ncol = wn * 64 + jn * 8 + g;
            uint32_t bH0 = buf[3072 + ncol * 12 + t4];
            uint32_t bH1 = buf[3072 + ncol * 12 + 4 + t4];
            uint32_t bL0 = buf[4608 + ncol * 12 + t4];
            uint32_t bL1 = buf[4608 + ncol * 12 + 4 + t4];
            #pragma unroll
            for (int im = 0; im < 2; im++) {
                mma16816(acc[im][jn], aH[im], bH0, bH1);
                mma16816(acc[im][jn], aL[im], bH0, bH1);
                mma16816(acc[im][jn], aH[im], bL0, bL1);
            }
        }
    }

    // ---- epilogue: bias + ReLU, direct store in [c][p] layout --------------
    #pragma unroll
    for (int im = 0; im < 2; im++) {
        const int mb = m0 + wm * 32 + im * 16;
        const float bb0 = __ldg(bsel + mb + g);
        const float bb1 = __ldg(bsel + mb + g + 8);
        #pragma unroll
        for (int jn = 0; jn < 8; jn++) {
            const int n = n0 + wn * 64 + jn * 8 + t4 * 2;
            float2 v0 = { fmaxf(acc[im][jn][0] + bb0, 0.f),
                          fmaxf(acc[im][jn][1] + bb0, 0.f) };
            float2 v1 = { fmaxf(acc[im][jn][2] + bb1, 0.f),
                          fmaxf(acc[im][jn][3] + bb1, 0.f) };
            *(float2*)(dst + (size_t)(mb + g    ) * HW_ + n) = v0;
            *(float2*)(dst + (size_t)(mb + g + 8) * HW_ + n) = v1;
        }
    }
}

// ---------------- kernel 2: K/V layout transpose into x_Kw / x_Vw ----------
// in:  scr[b][c][p]   out: [b][j][i] with j = (c&1)*16384 + p, i = c>>1
// grid (512, 4, 32): x = p-tile, y = i-tile, z = (b<<2)|(par<<1)|kv
__global__ void transpose_kv_kernel(float* __restrict__ ktw, float* __restrict__ vtw)
{
    __shared__ float tile[32][33];
    if (!ktw) ktw = g_ktfb;
    if (!vtw) vtw = g_vtfb;
    const int z   = blockIdx.z;
    const int kv  = z & 1;
    const int par = (z >> 1) & 1;
    const int b   = z >> 2;
    const float* src = (kv ? g_vscr : g_kscr) + (size_t)b * CHW_;
    float*       dst = (kv ? vtw    : ktw   ) + (size_t)b * CHW_;
    const int p0 = blockIdx.x << 5, i0 = blockIdx.y << 5;
    const int tx = threadIdx.x, ty = threadIdx.y;
    #pragma unroll
    for (int r = 0; r < 4; r++) {
        const int ii = ty + r * 8;
        tile[ii][tx] = src[(size_t)(2 * (i0 + ii) + par) * HW_ + p0 + tx];
    }
    __syncthreads();
    #pragma unroll
    for (int r = 0; r < 4; r++) {
        const int pp = ty + r * 8;
        dst[(size_t)(par * 16384 + p0 + pp) * 128 + i0 + tx] = tile[tx][pp];
    }
}

// ---------------- kernel 3: split-K logit GEMM  att_raw = Qr * Kr^T --------
// grid (SPLITK_, 8): x = k-split s, y = batch. Partial [128x128] -> g_psum.
__global__ __launch_bounds__(256, 2) void att_gemm_kernel(
    const float* __restrict__ q, const float* __restrict__ kt)
{
    __shared__ uint32_t sm[12288];
    if (!q)  q  = g_qfb;
    if (!kt) kt = g_ktfb;
    const int s = blockIdx.x, b = blockIdx.y;

    HACC_INIT(acc);
    hmma_gemm128(q  + (size_t)b * CHW_ + (size_t)s * KCH_, JD_,
                 kt + (size_t)b * CHW_ + (size_t)s * KCH_ * 128, 128,
                 16, acc, sm);

    float* Cp = g_psum + ((size_t)b * SPLITK_ + s) * 16384;
    const int lane = threadIdx.x & 31, w = threadIdx.x >> 5;
    const int g = lane >> 2, t4 = lane & 3, wm = w & 3, wn = w >> 2;
    #pragma unroll
    for (int im = 0; im < 2; im++) {
        const int mb = wm * 32 + im * 16;
        #pragma unroll
        for (int jn = 0; jn < 8; jn++) {
            const int n = wn * 64 + jn * 8 + t4 * 2;
            *(float2*)(Cp + (size_t)(mb + g    ) * 128 + n) =
                make_float2(acc[im][jn][0], acc[im][jn][1]);
            *(float2*)(Cp + (size_t)(mb + g + 8) * 128 + n) =
                make_float2(acc[im][jn][2], acc[im][jn][3]);
        }
    }
}

// ---------------- kernel 4: Kahan split-K reduce + softmax over axis=1 -----
// grid (128, 8): x = i' (column), y = batch; 128 threads = i (row)
__global__ void softmax_kernel(float* __restrict__ attw,
                               float* __restrict__ gmw,
                               const float* __restrict__ gamma)
{
    const int b = blockIdx.y, ip = blockIdx.x, i = threadIdx.x;
    const float* base = g_psum + (size_t)b * SPLITK_ * 16384 + (size_t)i * 128 + ip;
    float s = 0.f, comp = 0.f;
    for (int t = 0; t < SPLITK_; t++) {
        float y = __fsub_rn(base[(size_t)t * 16384], comp);
        float u = __fadd_rn(s, y);
        comp = __fsub_rn(__fsub_rn(u, s), y);
        s = u;
    }
    __shared__ float red[128];
    red[i] = s;
    __syncthreads();
    for (int off = 64; off > 0; off >>= 1) {
        if (i < off) red[i] = fmaxf(red[i], red[i + off]);
        __syncthreads();
    }
    const float mx = red[0];
    __syncthreads();
    const float e = expf(s - mx);
    red[i] = e;
    __syncthreads();
    for (int off = 64; off > 0; off >>= 1) {
        if (i < off) red[i] += red[i + off];
        __syncthreads();
    }
    const float r = e / red[0];
    g_att[(size_t)b * 16384 + (size_t)i * 128 + ip] = r;
    if (attw) attw[(size_t)b * 16384 + (size_t)i * 128 + ip] = r;
    if (gmw && b == 0 && ip == 0 && i == 0) *gmw = __ldg(gamma);
}

// ---------------- kernel 5: out1 = x_Vw @ att, scaled by gamma -------------
// grid (256, 8): x = m-tile (of 32768), y = batch
__global__ __launch_bounds__(256, 2) void out_gemm_kernel(
    const float* __restrict__ vt, float* __restrict__ outw,
    const float* __restrict__ gamma)
{
    __shared__ uint32_t sm[12288];
    if (!vt) vt = g_vtfb;
    const int b  = blockIdx.y;
    const int m0 = blockIdx.x << 7;

    HACC_INIT(acc);
    hmma_gemm128(vt + (size_t)b * CHW_ + (size_t)m0 * 128, 128,
                 g_att + (size_t)b * 16384, 128, 8, acc, sm);

    const float gsc = __ldg(gamma);
    float* base = outw + (size_t)b * CHW_;
    const int lane = threadIdx.x & 31, w = threadIdx.x >> 5;
    const int g = lane >> 2, t4 = lane & 3, wm = w & 3, wn = w >> 2;
    #pragma unroll
    for (int im = 0; im < 2; im++) {
        const int mb = m0 + wm * 32 + im * 16;
        #pragma unroll
        for (int jn = 0; jn < 8; jn++) {
            const int n = wn * 64 + jn * 8 + t4 * 2;
            *(float2*)(base + (size_t)(mb + g    ) * 128 + n) =
                make_float2(acc[im][jn][0] * gsc, acc[im][jn][1] * gsc);
            *(float2*)(base + (size_t)(mb + g + 8) * 128 + n) =
                make_float2(acc[im][jn][2] * gsc, acc[im][jn][3] * gsc);
        }
    }
}

// ---------------- launch ---------------------------------------------------
extern "C" void kernel_launch(void* const* d_in, const int* in_sizes, int n_in,
                              void* d_out, int out_size)
{
    const float* x  = (const float*)d_in[0];
    const float* Wq = (const float*)d_in[1];
    const float* bq = (const float*)d_in[2];
    const float* Wk = (const float*)d_in[3];
    const float* bk = (const float*)d_in[4];
    const float* Wv = (const float*)d_in[5];
    const float* bv = (const float*)d_in[6];
    const float* gm = (const float*)d_in[7];
    float* out = (float*)d_out;

    const bool full = (out_size >= FULL_SIZE);
    float* outw = out;  // out_w is the first tuple element either way
    float* qw   = full ? out + OFF_QW    : nullptr;
    float* ktw  = full ? out + OFF_KW    : nullptr;
    float* vtw  = full ? out + OFF_VW    : nullptr;
    float* gmw  = full ? out + OFF_GAMMA : nullptr;
    float* attw = full ? out + OFF_ATT   : nullptr;

    wsplit_kernel<<<384, 256>>>(Wq, Wk, Wv);
    conv_qkv_kernel<<<dim3(128, 6, 8), 256>>>(x, bq, bk, bv, qw);
    transpose_kv_kernel<<<dim3(512, 4, 32), dim3(32, 8)>>>(ktw, vtw);
    att_gemm_kernel<<<dim3(SPLITK_, 8), 256>>>(qw, ktw);
    softmax_kernel<<<dim3(128, 8), 128>>>(attw, gmw, gm);
    out_gemm_kernel<<<dim3(256, 8), 256>>>(vtw, outw, gm);
}

// round 12
// speedup vs baseline: 1.1267x; 1.1267x over previous
#include <cuda_runtime.h>
#include <cuda_bf16.h>
#include <cstdint>

// Problem constants
#define HW_     16384            // H*W
#define CHW_    4194304          // C*H*W
#define NB_     8
#define JD_     32768
#define SPLITK_ 128
#define KCH_    256

// Output chunk offsets (floats): (out_w, x_Qw, x_Kw, x_Vw, gamma, att)
#define OFF_OUTW  0
#define OFF_QW    33554432
#define OFF_KW    67108864
#define OFF_VW    100663296
#define OFF_GAMMA 134217728
#define OFF_ATT   134217729
#define FULL_SIZE 134348801

// ---------------- device-global scratch ------------------------------------
__device__ float g_kscr[(size_t)NB_ * CHW_];             // K conv fp32 natural
__device__ float g_vscr[(size_t)NB_ * CHW_];             // V conv fp32 natural
__device__ float g_psum[(size_t)NB_ * SPLITK_ * 16384];  // split-K partials
__device__ uint32_t g_whi[3 * 256 * 128];                // W hi bf16x2 [op][m][k/2]
__device__ uint32_t g_wlo[3 * 256 * 128];
__device__ uint32_t g_xh[(size_t)NB_ * CHW_ / 2];        // x^T bf16x2 [b][p][c/2]
__device__ uint32_t g_xl[(size_t)NB_ * CHW_ / 2];
__device__ uint32_t g_qh[(size_t)NB_ * CHW_ / 2];        // Q bf16x2 [b][c][p/2]
__device__ uint32_t g_ql[(size_t)NB_ * CHW_ / 2];
__device__ uint32_t g_kh[(size_t)NB_ * CHW_ / 2];        // K bf16x2 [b][c][p/2]
__device__ uint32_t g_kl[(size_t)NB_ * CHW_ / 2];
__device__ __nv_bfloat16 g_vth[(size_t)NB_ * CHW_];      // Vt bf16 [b][j][i]
__device__ __nv_bfloat16 g_vtl[(size_t)NB_ * CHW_];
__device__ __nv_bfloat16 g_ath[NB_ * 16384];             // att^T bf16 [b][j'][i]
__device__ __nv_bfloat16 g_atl[NB_ * 16384];

// ---------------- helpers ---------------------------------------------------
__device__ __forceinline__ void split2(float x, float y, uint32_t& hi, uint32_t& lo) {
    __nv_bfloat16 hx = __float2bfloat16_rn(x);
    __nv_bfloat16 hy = __float2bfloat16_rn(y);
    __nv_bfloat162 h; h.x = hx; h.y = hy;
    hi = *reinterpret_cast<uint32_t*>(&h);
    __nv_bfloat162 l = __floats2bfloat162_rn(x - __bfloat162float(hx),
                                             y - __bfloat162float(hy));
    lo = *reinterpret_cast<uint32_t*>(&l);
}

__device__ __forceinline__ void mma16816(float* c, const uint32_t a[4],
                                         uint32_t b0, uint32_t b1) {
    asm("mma.sync.aligned.m16n8k16.row.col.f32.bf16.bf16.f32 "
        "{%0,%1,%2,%3}, {%4,%5,%6,%7}, {%8,%9}, {%0,%1,%2,%3};"
        : "+f"(c[0]), "+f"(c[1]), "+f"(c[2]), "+f"(c[3])
        : "r"(a[0]), "r"(a[1]), "r"(a[2]), "r"(a[3]), "r"(b0), "r"(b1));
}

__device__ __forceinline__ void cpa16(uint32_t s, const void* g) {
    asm volatile("cp.async.ca.shared.global [%0], [%1], 16;" :: "r"(s), "l"(g));
}
#define CP_COMMIT() asm volatile("cp.async.commit_group;" ::: "memory")
#define CP_WAIT1()  asm volatile("cp.async.wait_group 1;"  ::: "memory")

__device__ __forceinline__ void ldm_x4(uint32_t* r, uint32_t a) {
    asm volatile("ldmatrix.sync.aligned.m8n8.x4.shared.b16 {%0,%1,%2,%3}, [%4];"
        : "=r"(r[0]), "=r"(r[1]), "=r"(r[2]), "=r"(r[3]) : "r"(a));
}

#define HACC_INIT(acc)                                         \
    float acc[2][8][4];                                        \
    _Pragma("unroll")                                          \
    for (int _i = 0; _i < 2; _i++)                             \
        _Pragma("unroll")                                      \
        for (int _j = 0; _j < 8; _j++)                         \
            _Pragma("unroll")                                  \
            for (int _e = 0; _e < 4; _e++) acc[_i][_j][_e] = 0.f;

// ---------------- cp.async + ldmatrix HMMA core -----------------------------
// C[128,128] += Ahl[128,K] * Bhl[K,128], 3-pass bf16 hi/lo.
// Plane gmem layout: rows (A: m, B: n) of bf16 k-contiguous; 32B per chunk.
// smem: 2 stages x 4 planes(Ah,Al,Bh,Bl) x 128 rows x 48B (32B data + pad).
// 8 warps 4(m) x 2(n); frag loads via ldmatrix.x4; staging via cp.async.
__device__ __forceinline__ void hmma_core(
    const char* gAh, const char* gAl, size_t ldA,
    const char* gBh, const char* gBl, size_t ldB,
    int nChunks, float acc[2][8][4], uint32_t* smraw)
{
    const int tid = threadIdx.x;
    uint32_t sb;
    asm("{ .reg .u64 t; cvta.to.shared.u64 t, %1; cvt.u32.u64 %0, t; }"
        : "=r"(sb) : "l"(smraw));

    // staging mapping: plane = tid>>6, rows 2*(tid&63), 2*(tid&63)+1
    const int spl = tid >> 6;
    const int srw = (tid & 63) << 1;
    const char* gb = (spl == 0) ? gAh : (spl == 1) ? gAl : (spl == 2) ? gBh : gBl;
    const size_t ld = (spl < 2) ? ldA : ldB;
    const char* g0 = gb + (size_t)srw * ld;
    const char* g1 = g0 + ld;
    const uint32_t s0 = sb + spl * 6144 + srw * 48;
    const uint32_t s1 = s0 + 48;

#define STG_(ch, bo) do {                                                     \
    const char* _p0 = g0 + (size_t)(ch) * 32;                                 \
    const char* _p1 = g1 + (size_t)(ch) * 32;                                 \
    cpa16(s0 + (bo), _p0); cpa16(s0 + (bo) + 16, _p0 + 16);                   \
    cpa16(s1 + (bo), _p1); cpa16(s1 + (bo) + 16, _p1 + 16); } while (0)

    // fragment ldmatrix addresses
    const int lane = tid & 31, w = tid >> 5;
    const int wm = w & 3, wn = w >> 2;
    const int l7 = lane & 7, lb8 = (lane >> 3) & 1, lb16 = lane >> 4;
    const uint32_t aA0 = sb + (uint32_t)(wm * 32 + l7 + lb8 * 8) * 48 + lb16 * 16;
    const uint32_t aA1 = aA0 + 16 * 48;
    const uint32_t bA  = sb + 12288 + (uint32_t)(wn * 64 + lb16 * 8 + l7) * 48 + lb8 * 16;

    STG_(0, 0); CP_COMMIT();
    STG_(1, 24576); CP_COMMIT();

    #pragma unroll 1
    for (int ch = 0; ch < nChunks; ch++) {
        CP_WAIT1();
        __syncthreads();
        const uint32_t bo = (uint32_t)(ch & 1) * 24576;

        uint32_t aH0[4], aH1[4], aL0[4], aL1[4];
        ldm_x4(aH0, aA0 + bo);
        ldm_x4(aH1, aA1 + bo);
        ldm_x4(aL0, aA0 + bo + 6144);
        ldm_x4(aL1, aA1 + bo + 6144);
        #pragma unroll
        for (int jp = 0; jp < 4; jp++) {
            uint32_t bh[4], bl[4];
            ldm_x4(bh, bA + bo + jp * 768);
            ldm_x4(bl, bA + bo + jp * 768 + 6144);
            mma16816(acc[0][2*jp],   aH0, bh[0], bh[1]);
            mma16816(acc[1][2*jp],   aH1, bh[0], bh[1]);
            mma16816(acc[0][2*jp],   aL0, bh[0], bh[1]);
            mma16816(acc[1][2*jp],   aL1, bh[0], bh[1]);
            mma16816(acc[0][2*jp],   aH0, bl[0], bl[1]);
            mma16816(acc[1][2*jp],   aH1, bl[0], bl[1]);
            mma16816(acc[0][2*jp+1], aH0, bh[2], bh[3]);
            mma16816(acc[1][2*jp+1], aH1, bh[2], bh[3]);
            mma16816(acc[0][2*jp+1], aL0, bh[2], bh[3]);
            mma16816(acc[1][2*jp+1], aL1, bh[2], bh[3]);
            mma16816(acc[0][2*jp+1], aH0, bl[2], bl[3]);
            mma16816(acc[1][2*jp+1], aH1, bl[2], bl[3]);
        }
        __syncthreads();
        if (ch + 2 < nChunks) STG_(ch + 2, bo);
        CP_COMMIT();
    }
#undef STG_
}

// ---------------- prep kernel: W pre-split ----------------------------------
__global__ void wsplit_kernel(const float* __restrict__ Wq,
                              const float* __restrict__ Wk,
                              const float* __restrict__ Wv)
{
    const int idx = blockIdx.x * 256 + threadIdx.x;   // 98304
    const int op  = idx >> 15;
    const int rem = idx & 32767;
    const float* W = (op == 0) ? Wq : (op == 1) ? Wk : Wv;
    float2 v = *(const float2*)(W + (size_t)rem * 2);
    uint32_t hi, lo;
    split2(v.x, v.y, hi, lo);
    g_whi[idx] = hi;
    g_wlo[idx] = lo;
}

// ---------------- prep kernel: x transpose + pre-split -----------------------
// x[b][c][p] fp32 -> g_xh/g_xl [b][p][c/2] bf16x2
// grid (512, 4, 8): p-tile 32, c-tile 64, batch; block (32, 8)
__global__ void xsplit_kernel(const float* __restrict__ x)
{
    __shared__ float t[64][33];
    const int b = blockIdx.z;
    const int p0 = blockIdx.x << 5;
    const int c0 = blockIdx.y << 6;
    const int tx = threadIdx.x, ty = threadIdx.y;
    const float* xb = x + (size_t)b * CHW_;
    #pragma unroll
    for (int r = 0; r < 8; r++) {
        const int cc = ty + r * 8;
        t[cc][tx] = xb[(size_t)(c0 + cc) * HW_ + p0 + tx];
    }
    __syncthreads();
    uint32_t* oh = g_xh + (size_t)b * (CHW_ / 2);
    uint32_t* ol = g_xl + (size_t)b * (CHW_ / 2);
    #pragma unroll
    for (int r = 0; r < 4; r++) {
        const int pp = ty + r * 8;
        uint32_t hi, lo;
        split2(t[2 * tx][pp], t[2 * tx + 1][pp], hi, lo);
        const size_t o = (size_t)(p0 + pp) * 128 + (c0 >> 1) + tx;
        oh[o] = hi;
        ol[o] = lo;
    }
}

// ---------------- kernel 1: QKV conv + bias + ReLU ---------------------------
// grid (128, 6, 8). Reads pre-split W and x planes via cp.async core.
// Epilogue: fp32 outputs + bf16 hi/lo planes for Q and K (natural layout).
__global__ __launch_bounds__(256, 2) void conv_qkv_kernel(
    const float* __restrict__ bq, const float* __restrict__ bk,
    const float* __restrict__ bv, float* __restrict__ qdst)
{
    __shared__ __align__(16) uint32_t smb[12288];
    const int tid = threadIdx.x, lane = tid & 31, w = tid >> 5;
    const int g = lane >> 2, t4 = lane & 3, wm = w & 3, wn = w >> 2;
    const int b = blockIdx.z, op = blockIdx.y >> 1;
    const int m0 = (blockIdx.y & 1) << 7, n0 = blockIdx.x << 7;

    const uint32_t* Ah = g_whi + op * 32768 + m0 * 128;
    const uint32_t* Al = g_wlo + op * 32768 + m0 * 128;
    const uint32_t* Bh = g_xh + (size_t)b * (CHW_ / 2) + (size_t)n0 * 128;
    const uint32_t* Bl = g_xl + (size_t)b * (CHW_ / 2) + (size_t)n0 * 128;

    HACC_INIT(acc);
    hmma_core((const char*)Ah, (const char*)Al, 512,
              (const char*)Bh, (const char*)Bl, 512, 16, acc, smb);

    const float* bsel = (op == 0) ? bq : (op == 1) ? bk : bv;
    float* dstf = (op == 0) ? qdst : (op == 1) ? g_kscr : g_vscr;
    if (dstf) dstf += (size_t)b * CHW_;
    uint32_t* ph = (op == 0) ? g_qh : (op == 1) ? g_kh : nullptr;
    uint32_t* pl = (op == 0) ? g_ql : (op == 1) ? g_kl : nullptr;
    if (ph) { ph += (size_t)b * (CHW_ / 2); pl += (size_t)b * (CHW_ / 2); }

    #pragma unroll
    for (int im = 0; im < 2; im++) {
        const int mb = m0 + wm * 32 + im * 16;
        const float bb0 = __ldg(bsel + mb + g);
        const float bb1 = __ldg(bsel + mb + g + 8);
        #pragma unroll
        for (int jn = 0; jn < 8; jn++) {
            const int n = n0 + wn * 64 + jn * 8 + t4 * 2;
            float2 v0 = { fmaxf(acc[im][jn][0] + bb0, 0.f),
                          fmaxf(acc[im][jn][1] + bb0, 0.f) };
            float2 v1 = { fmaxf(acc[im][jn][2] + bb1, 0.f),
                          fmaxf(acc[im][jn][3] + bb1, 0.f) };
            const size_t r0 = (size_t)(mb + g) * HW_ + n;
            const size_t r1 = (size_t)(mb + g + 8) * HW_ + n;
            if (dstf) {
                *(float2*)(dstf + r0) = v0;
                *(float2*)(dstf + r1) = v1;
            }
            if (ph) {
                uint32_t hi, lo;
                split2(v0.x, v0.y, hi, lo);
                ph[r0 >> 1] = hi; pl[r0 >> 1] = lo;
                split2(v1.x, v1.y, hi, lo);
                ph[r1 >> 1] = hi; pl[r1 >> 1] = lo;
            }
        }
    }
}

// ---------------- kernel 2: K/V transpose (+ Vt bf16 planes) -----------------
// grid (512, 4, 32): z = (b<<2)|(par<<1)|kv
__global__ void transpose_kv_kernel(float* __restrict__ ktw, float* __restrict__ vtw)
{
    __shared__ float tile[32][33];
    const int z   = blockIdx.z;
    const int kv  = z & 1;
    const int par = (z >> 1) & 1;
    const int b   = z >> 2;
    float* dstf = kv ? vtw : ktw;
    if (!kv && !dstf) return;       // K half only produces the fp32 output
    const float* src = (kv ? g_vscr : g_kscr) + (size_t)b * CHW_;
    const int p0 = blockIdx.x << 5, i0 = blockIdx.y << 5;
    const int tx = threadIdx.x, ty = threadIdx.y;
    #pragma unroll
    for (int r = 0; r < 4; r++) {
        const int ii = ty + r * 8;
        tile[ii][tx] = src[(size_t)(2 * (i0 + ii) + par) * HW_ + p0 + tx];
    }
    __syncthreads();
    const size_t bofs = (size_t)b * CHW_;
    #pragma unroll
    for (int r = 0; r < 4; r++) {
        const int pp = ty + r * 8;
        const size_t idx = (size_t)(par * 16384 + p0 + pp) * 128 + i0 + tx;
        const float v = tile[tx][pp];
        if (dstf) dstf[bofs + idx] = v;
        if (kv) {
            __nv_bfloat16 h = __float2bfloat16_rn(v);
            g_vth[bofs + idx] = h;
            g_vtl[bofs + idx] = __float2bfloat16_rn(v - __bfloat162float(h));
        }
    }
}

// ---------------- kernel 3: split-K logit GEMM -------------------------------
// grid (SPLITK_, 8). A = Q planes, B = K planes (both natural layout).
__global__ __launch_bounds__(256, 2) void att_gemm_kernel()
{
    __shared__ __align__(16) uint32_t smb[12288];
    const int s = blockIdx.x, b = blockIdx.y;
    const size_t base = (size_t)b * (CHW_ / 2) + (size_t)(s >> 6) * 8192
                      + (size_t)(s & 63) * 128;

    HACC_INIT(acc);
    hmma_core((const char*)(g_qh + base), (const char*)(g_ql + base), 65536,
              (const char*)(g_kh + base), (const char*)(g_kl + base), 65536,
              16, acc, smb);

    float* Cp = g_psum + ((size_t)b * SPLITK_ + s) * 16384;
    const int lane = threadIdx.x & 31, w = threadIdx.x >> 5;
    const int g = lane >> 2, t4 = lane & 3, wm = w & 3, wn = w >> 2;
    #pragma unroll
    for (int im = 0; im < 2; im++) {
        const int mb = wm * 32 + im * 16;
        #pragma unroll
        for (int jn = 0; jn < 8; jn++) {
            const int n = wn * 64 + jn * 8 + t4 * 2;
            *(float2*)(Cp + (size_t)(mb + g    ) * 128 + n) =
                make_float2(acc[im][jn][0], acc[im][jn][1]);
            *(float2*)(Cp + (size_t)(mb + g + 8) * 128 + n) =
                make_float2(acc[im][jn][2], acc[im][jn][3]);
        }
    }
}

// ---------------- kernel 4: Kahan reduce + softmax (+ att bf16 planes) -------
// grid (128, 8): x = j' column, y = batch; 128 threads = i row
__global__ void softmax_kernel(float* __restrict__ attw,
                               float* __restrict__ gmw,
                               const float* __restrict__ gamma)
{
    const int b = blockIdx.y, ip = blockIdx.x, i = threadIdx.x;
    const float* base = g_psum + (size_t)b * SPLITK_ * 16384 + (size_t)i * 128 + ip;
    float s = 0.f, comp = 0.f;
    for (int t = 0; t < SPLITK_; t++) {
        float y = __fsub_rn(base[(size_t)t * 16384], comp);
        float u = __fadd_rn(s, y);
        comp = __fsub_rn(__fsub_rn(u, s), y);
        s = u;
    }
    __shared__ float red[128];
    red[i] = s;
    __syncthreads();
    for (int off = 64; off > 0; off >>= 1) {
        if (i < off) red[i] = fmaxf(red[i], red[i + off]);
        __syncthreads();
    }
    const float mx = red[0];
    __syncthreads();
    const float e = expf(s - mx);
    red[i] = e;
    __syncthreads();
    for (int off = 64; off > 0; off >>= 1) {
        if (i < off) red[i] += red[i + off];
        __syncthreads();
    }
    const float r = e / red[0];
    __nv_bfloat16 h = __float2bfloat16_rn(r);
    g_ath[(size_t)b * 16384 + (size_t)ip * 128 + i] = h;   // transposed [j'][i]
    g_atl[(size_t)b * 16384 + (size_t)ip * 128 + i] =
        __float2bfloat16_rn(r - __bfloat162float(h));
    if (attw) attw[(size_t)b * 16384 + (size_t)i * 128 + ip] = r;
    if (gmw && b == 0 && ip == 0 && i == 0) *gmw = __ldg(gamma);
}

// ---------------- kernel 5: out = Vt @ att, scaled by gamma ------------------
// grid (256, 8). A = Vt planes [j][i], B = att planes [j'][i].
__global__ __launch_bounds__(256, 2) void out_gemm_kernel(
    float* __restrict__ outw, const float* __restrict__ gamma)
{
    __shared__ __align__(16) uint32_t smb[12288];
    const int b  = blockIdx.y;
    const int m0 = blockIdx.x << 7;
    const char* Ah = (const char*)(g_vth + (size_t)b * CHW_ + (size_t)m0 * 128);
    const char* Al = (const char*)(g_vtl + (size_t)b * CHW_ + (size_t)m0 * 128);
    const char* Bh = (const char*)(g_ath + (size_t)b * 16384);
    const char* Bl = (const char*)(g_atl + (size_t)b * 16384);

    HACC_INIT(acc);
    hmma_core(Ah, Al, 256, Bh, Bl, 256, 8, acc, smb);

    const float gsc = __ldg(gamma);
    float* base = outw + (size_t)b * CHW_;
    const int lane = threadIdx.x & 31, w = threadIdx.x >> 5;
    const int g = lane >> 2, t4 = lane & 3, wm = w & 3, wn = w >> 2;
    #pragma unroll
    for (int im = 0; im < 2; im++) {
        const int mb = m0 + wm * 32 + im * 16;
        #pragma unroll
        for (int jn = 0; jn < 8; jn++) {
            const int n = wn * 64 + jn * 8 + t4 * 2;
            *(float2*)(base + (size_t)(mb + g    ) * 128 + n) =
                make_float2(acc[im][jn][0] * gsc, acc[im][jn][1] * gsc);
            *(float2*)(base + (size_t)(mb + g + 8) * 128 + n) =
                make_float2(acc[im][jn][2] * gsc, acc[im][jn][3] * gsc);
        }
    }
}

// ---------------- launch -----------------------------------------------------
extern "C" void kernel_launch(void* const* d_in, const int* in_sizes, int n_in,
                              void* d_out, int out_size)
{
    const float* x  = (const float*)d_in[0];
    const float* Wq = (const float*)d_in[1];
    const float* bq = (const float*)d_in[2];
    const float* Wk = (const float*)d_in[3];
    const float* bk = (const float*)d_in[4];
    const float* Wv = (const float*)d_in[5];
    const float* bv = (const float*)d_in[6];
    const float* gm = (const float*)d_in[7];
    float* out = (float*)d_out;

    const bool full = (out_size >= FULL_SIZE);
    float* outw = out;
    float* qw   = full ? out + OFF_QW    : nullptr;
    float* ktw  = full ? out + OFF_KW    : nullptr;
    float* vtw  = full ? out + OFF_VW    : nullptr;
    float* gmw  = full ? out + OFF_GAMMA : nullptr;
    float* attw = full ? out + OFF_ATT   : nullptr;

    wsplit_kernel<<<384, 256>>>(Wq, Wk, Wv);
    xsplit_kernel<<<dim3(512, 4, 8), dim3(32, 8)>>>(x);
    conv_qkv_kernel<<<dim3(128, 6, 8), 256>>>(bq, bk, bv, qw);
    transpose_kv_kernel<<<dim3(512, 4, 32), dim3(32, 8)>>>(ktw, vtw);
    att_gemm_kernel<<<dim3(SPLITK_, 8), 256>>>();
    softmax_kernel<<<dim3(128, 8), 128>>>(attw, gmw, gm);
    out_gemm_kernel<<<dim3(256, 8), 256>>>(outw, gm);
}

// round 15
// speedup vs baseline: 1.1289x; 1.0019x over previous
#include <cuda_runtime.h>
#include <cuda_bf16.h>
#include <cstdint>

// Problem constants
#define HW_     16384            // H*W
#define CHW_    4194304          // C*H*W
#define NB_     8
#define JD_     32768
#define SPLITK_ 128
#define KCH_    256

// Output chunk offsets (floats): (out_w, x_Qw, x_Kw, x_Vw, gamma, att)
#define OFF_OUTW  0
#define OFF_QW    33554432
#define OFF_KW    67108864
#define OFF_VW    100663296
#define OFF_GAMMA 134217728
#define OFF_ATT   134217729
#define FULL_SIZE 134348801

// ---------------- device-global scratch ------------------------------------
__device__ float g_kscr[(size_t)NB_ * CHW_];             // K conv fp32 natural
__device__ float g_vscr[(size_t)NB_ * CHW_];             // V conv fp32 natural
__device__ float g_psum[(size_t)NB_ * SPLITK_ * 16384];  // split-K partials
__device__ uint32_t g_whi[3 * 256 * 128];                // W hi bf16x2 [op][m][k/2]
__device__ uint32_t g_wlo[3 * 256 * 128];
__device__ uint32_t g_xh[(size_t)NB_ * CHW_ / 2];        // x^T bf16x2 [b][p][c/2]
__device__ uint32_t g_xl[(size_t)NB_ * CHW_ / 2];
__device__ uint32_t g_qh[(size_t)NB_ * CHW_ / 2];        // Q bf16x2 [b][c][p/2]
__device__ uint32_t g_ql[(size_t)NB_ * CHW_ / 2];
__device__ uint32_t g_kh[(size_t)NB_ * CHW_ / 2];        // K bf16x2 [b][c][p/2]
__device__ uint32_t g_kl[(size_t)NB_ * CHW_ / 2];
__device__ __nv_bfloat16 g_vth[(size_t)NB_ * CHW_];      // Vt bf16 [b][j][i]
__device__ __nv_bfloat16 g_vtl[(size_t)NB_ * CHW_];
__device__ __nv_bfloat16 g_ath[NB_ * 16384];             // att^T bf16 [b][j'][i]
__device__ __nv_bfloat16 g_atl[NB_ * 16384];

// ---------------- helpers ---------------------------------------------------
__device__ __forceinline__ void split2(float x, float y, uint32_t& hi, uint32_t& lo) {
    __nv_bfloat16 hx = __float2bfloat16_rn(x);
    __nv_bfloat16 hy = __float2bfloat16_rn(y);
    __nv_bfloat162 h; h.x = hx; h.y = hy;
    hi = *reinterpret_cast<uint32_t*>(&h);
    __nv_bfloat162 l = __floats2bfloat162_rn(x - __bfloat162float(hx),
                                             y - __bfloat162float(hy));
    lo = *reinterpret_cast<uint32_t*>(&l);
}

__device__ __forceinline__ void mma16816(float* c, const uint32_t a[4],
                                         uint32_t b0, uint32_t b1) {
    asm("mma.sync.aligned.m16n8k16.row.col.f32.bf16.bf16.f32 "
        "{%0,%1,%2,%3}, {%4,%5,%6,%7}, {%8,%9}, {%0,%1,%2,%3};"
        : "+f"(c[0]), "+f"(c[1]), "+f"(c[2]), "+f"(c[3])
        : "r"(a[0]), "r"(a[1]), "r"(a[2]), "r"(a[3]), "r"(b0), "r"(b1));
}

__device__ __forceinline__ void cpa16(uint32_t s, const void* g) {
    asm volatile("cp.async.ca.shared.global [%0], [%1], 16;" :: "r"(s), "l"(g));
}
#define CP_COMMIT() asm volatile("cp.async.commit_group;" ::: "memory")
#define CP_WAIT1()  asm volatile("cp.async.wait_group 1;"  ::: "memory")

__device__ __forceinline__ void ldm_x4(uint32_t* r, uint32_t a) {
    asm volatile("ldmatrix.sync.aligned.m8n8.x4.shared.b16 {%0,%1,%2,%3}, [%4];"
        : "=r"(r[0]), "=r"(r[1]), "=r"(r[2]), "=r"(r[3]) : "r"(a));
}

#define HACC_INIT(acc)                                         \
    float acc[2][8][4];                                        \
    _Pragma("unroll")                                          \
    for (int _i = 0; _i < 2; _i++)                             \
        _Pragma("unroll")                                      \
        for (int _j = 0; _j < 8; _j++)                         \
            _Pragma("unroll")                                  \
            for (int _e = 0; _e < 4; _e++) acc[_i][_j][_e] = 0.f;

// ---------------- cp.async + ldmatrix HMMA core -----------------------------
// C[128,128] += Ahl[128,K] * Bhl[K,128], 3-pass bf16 hi/lo.
// Plane gmem layout: rows (A: m, B: n) of bf16 k-contiguous; 32B per chunk.
// smem: 2 stages x 4 planes(Ah,Al,Bh,Bl) x 128 rows x 48B (32B data + pad).
// 8 warps 4(m) x 2(n); frag loads via ldmatrix.x4; staging via cp.async.
// MMA schedule: 3 phases of 16 INDEPENDENT MMAs (dep distance 16 per acc):
//   phase1 Ah*Bh over all 16 accs; phase2 Al*Bh; phase3 Ah*Bl.
// Per-acc accumulation order unchanged (AhBh, AlBh, AhBl) => bit-identical.
__device__ __forceinline__ void hmma_core(
    const char* gAh, const char* gAl, size_t ldA,
    const char* gBh, const char* gBl, size_t ldB,
    int nChunks, float acc[2][8][4], uint32_t* smraw)
{
    const int tid = threadIdx.x;
    uint32_t sb;
    asm("{ .reg .u64 t; cvta.to.shared.u64 t, %1; cvt.u32.u64 %0, t; }"
        : "=r"(sb) : "l"(smraw));

    // staging mapping: plane = tid>>6, rows 2*(tid&63), 2*(tid&63)+1
    const int spl = tid >> 6;
    const int srw = (tid & 63) << 1;
    const char* gb = (spl == 0) ? gAh : (spl == 1) ? gAl : (spl == 2) ? gBh : gBl;
    const size_t ld = (spl < 2) ? ldA : ldB;
    const char* g0 = gb + (size_t)srw * ld;
    const char* g1 = g0 + ld;
    const uint32_t s0 = sb + spl * 6144 + srw * 48;
    const uint32_t s1 = s0 + 48;

#define STG_(ch, bo) do {                                                     \
    const char* _p0 = g0 + (size_t)(ch) * 32;                                 \
    const char* _p1 = g1 + (size_t)(ch) * 32;                                 \
    cpa16(s0 + (bo), _p0); cpa16(s0 + (bo) + 16, _p0 + 16);                   \
    cpa16(s1 + (bo), _p1); cpa16(s1 + (bo) + 16, _p1 + 16); } while (0)

    // fragment ldmatrix addresses
    const int lane = tid & 31, w = tid >> 5;
    const int wm = w & 3, wn = w >> 2;
    const int l7 = lane & 7, lb8 = (lane >> 3) & 1, lb16 = lane >> 4;
    const uint32_t aA0 = sb + (uint32_t)(wm * 32 + l7 + lb8 * 8) * 48 + lb16 * 16;
    const uint32_t aA1 = aA0 + 16 * 48;
    const uint32_t bA  = sb + 12288 + (uint32_t)(wn * 64 + lb16 * 8 + l7) * 48 + lb8 * 16;

    STG_(0, 0); CP_COMMIT();
    STG_(1, 24576); CP_COMMIT();

    #pragma unroll 1
    for (int ch = 0; ch < nChunks; ch++) {
        CP_WAIT1();
        __syncthreads();
        const uint32_t bo = (uint32_t)(ch & 1) * 24576;

        uint32_t aH0[4], aH1[4], aL0[4], aL1[4];
        uint32_t bF[4][4];

        // ---- A-hi + B-hi fragments ----------------------------------------
        ldm_x4(aH0, aA0 + bo);
        ldm_x4(aH1, aA1 + bo);
        #pragma unroll
        for (int jp = 0; jp < 4; jp++) ldm_x4(bF[jp], bA + bo + jp * 768);

        // ---- phase 1: Ah * Bh (16 independent MMAs) -----------------------
        #pragma unroll
        for (int jp = 0; jp < 4; jp++) {
            mma16816(acc[0][2*jp],   aH0, bF[jp][0], bF[jp][1]);
            mma16816(acc[1][2*jp],   aH1, bF[jp][0], bF[jp][1]);
            mma16816(acc[0][2*jp+1], aH0, bF[jp][2], bF[jp][3]);
            mma16816(acc[1][2*jp+1], aH1, bF[jp][2], bF[jp][3]);
        }

        // ---- A-lo fragments (overlap with phase-1 drain) ------------------
        ldm_x4(aL0, aA0 + bo + 6144);
        ldm_x4(aL1, aA1 + bo + 6144);

        // ---- phase 2: Al * Bh ---------------------------------------------
        #pragma unroll
        for (int jp = 0; jp < 4; jp++) {
            mma16816(acc[0][2*jp],   aL0, bF[jp][0], bF[jp][1]);
            mma16816(acc[1][2*jp],   aL1, bF[jp][0], bF[jp][1]);
            mma16816(acc[0][2*jp+1], aL0, bF[jp][2], bF[jp][3]);
            mma16816(acc[1][2*jp+1], aL1, bF[jp][2], bF[jp][3]);
        }

        // ---- B-lo fragments -----------------------------------------------
        #pragma unroll
        for (int jp = 0; jp < 4; jp++) ldm_x4(bF[jp], bA + bo + jp * 768 + 6144);

        // ---- phase 3: Ah * Bl ---------------------------------------------
        #pragma unroll
        for (int jp = 0; jp < 4; jp++) {
            mma16816(acc[0][2*jp],   aH0, bF[jp][0], bF[jp][1]);
            mma16816(acc[1][2*jp],   aH1, bF[jp][0], bF[jp][1]);
            mma16816(acc[0][2*jp+1], aH0, bF[jp][2], bF[jp][3]);
            mma16816(acc[1][2*jp+1], aH1, bF[jp][2], bF[jp][3]);
        }

        __syncthreads();
        if (ch + 2 < nChunks) STG_(ch + 2, bo);
        CP_COMMIT();
    }
#undef STG_
}

// ---------------- prep kernel: W pre-split ----------------------------------
__global__ void wsplit_kernel(const float* __restrict__ Wq,
                              const float* __restrict__ Wk,
                              const float* __restrict__ Wv)
{
    const int idx = blockIdx.x * 256 + threadIdx.x;   // 98304
    const int op  = idx >> 15;
    const int rem = idx & 32767;
    const float* W = (op == 0) ? Wq : (op == 1) ? Wk : Wv;
    float2 v = *(const float2*)(W + (size_t)rem * 2);
    uint32_t hi, lo;
    split2(v.x, v.y, hi, lo);
    g_whi[idx] = hi;
    g_wlo[idx] = lo;
}

// ---------------- prep kernel: x transpose + pre-split -----------------------
// x[b][c][p] fp32 -> g_xh/g_xl [b][p][c/2] bf16x2
// grid (512, 4, 8): p-tile 32, c-tile 64, batch; block (32, 8)
__global__ void xsplit_kernel(const float* __restrict__ x)
{
    __shared__ float t[64][33];
    const int b = blockIdx.z;
    const int p0 = blockIdx.x << 5;
    const int c0 = blockIdx.y << 6;
    const int tx = threadIdx.x, ty = threadIdx.y;
    const float* xb = x + (size_t)b * CHW_;
    #pragma unroll
    for (int r = 0; r < 8; r++) {
        const int cc = ty + r * 8;
        t[cc][tx] = xb[(size_t)(c0 + cc) * HW_ + p0 + tx];
    }
    __syncthreads();
    uint32_t* oh = g_xh + (size_t)b * (CHW_ / 2);
    uint32_t* ol = g_xl + (size_t)b * (CHW_ / 2);
    #pragma unroll
    for (int r = 0; r < 4; r++) {
        const int pp = ty + r * 8;
        uint32_t hi, lo;
        split2(t[2 * tx][pp], t[2 * tx + 1][pp], hi, lo);
        const size_t o = (size_t)(p0 + pp) * 128 + (c0 >> 1) + tx;
        oh[o] = hi;
        ol[o] = lo;
    }
}

// ---------------- kernel 1: QKV conv + bias + ReLU ---------------------------
// grid (128, 6, 8). Reads pre-split W and x planes via cp.async core.
// Epilogue: fp32 outputs + bf16 hi/lo planes for Q and K (natural layout).
__global__ __launch_bounds__(256, 2) void conv_qkv_kernel(
    const float* __restrict__ bq, const float* __restrict__ bk,
    const float* __restrict__ bv, float* __restrict__ qdst)
{
    __shared__ __align__(16) uint32_t smb[12288];
    const int tid = threadIdx.x, lane = tid & 31, w = tid >> 5;
    const int g = lane >> 2, t4 = lane & 3, wm = w & 3, wn = w >> 2;
    const int b = blockIdx.z, op = blockIdx.y >> 1;
    const int m0 = (blockIdx.y & 1) << 7, n0 = blockIdx.x << 7;

    const uint32_t* Ah = g_whi + op * 32768 + m0 * 128;
    const uint32_t* Al = g_wlo + op * 32768 + m0 * 128;
    const uint32_t* Bh = g_xh + (size_t)b * (CHW_ / 2) + (size_t)n0 * 128;
    const uint32_t* Bl = g_xl + (size_t)b * (CHW_ / 2) + (size_t)n0 * 128;

    HACC_INIT(acc);
    hmma_core((const char*)Ah, (const char*)Al, 512,
              (const char*)Bh, (const char*)Bl, 512, 16, acc, smb);

    const float* bsel = (op == 0) ? bq : (op == 1) ? bk : bv;
    float* dstf = (op == 0) ? qdst : (op == 1) ? g_kscr : g_vscr;
    if (dstf) dstf += (size_t)b * CHW_;
    uint32_t* ph = (op == 0) ? g_qh : (op == 1) ? g_kh : nullptr;
    uint32_t* pl = (op == 0) ? g_ql : (op == 1) ? g_kl : nullptr;
    if (ph) { ph += (size_t)b * (CHW_ / 2); pl += (size_t)b * (CHW_ / 2); }

    #pragma unroll
    for (int im = 0; im < 2; im++) {
        const int mb = m0 + wm * 32 + im * 16;
        const float bb0 = __ldg(bsel + mb + g);
        const float bb1 = __ldg(bsel + mb + g + 8);
        #pragma unroll
        for (int jn = 0; jn < 8; jn++) {
            const int n = n0 + wn * 64 + jn * 8 + t4 * 2;
            float2 v0 = { fmaxf(acc[im][jn][0] + bb0, 0.f),
                          fmaxf(acc[im][jn][1] + bb0, 0.f) };
            float2 v1 = { fmaxf(acc[im][jn][2] + bb1, 0.f),
                          fmaxf(acc[im][jn][3] + bb1, 0.f) };
            const size_t r0 = (size_t)(mb + g) * HW_ + n;
            const size_t r1 = (size_t)(mb + g + 8) * HW_ + n;
            if (dstf) {
                *(float2*)(dstf + r0) = v0;
                *(float2*)(dstf + r1) = v1;
            }
            if (ph) {
                uint32_t hi, lo;
                split2(v0.x, v0.y, hi, lo);
                ph[r0 >> 1] = hi; pl[r0 >> 1] = lo;
                split2(v1.x, v1.y, hi, lo);
                ph[r1 >> 1] = hi; pl[r1 >> 1] = lo;
            }
        }
    }
}

// ---------------- kernel 2: K/V transpose (+ Vt bf16 planes) -----------------
// grid (512, 4, 32): z = (b<<2)|(par<<1)|kv
__global__ void transpose_kv_kernel(float* __restrict__ ktw, float* __restrict__ vtw)
{
    __shared__ float tile[32][33];
    const int z   = blockIdx.z;
    const int kv  = z & 1;
    const int par = (z >> 1) & 1;
    const int b   = z >> 2;
    float* dstf = kv ? vtw : ktw;
    if (!kv && !dstf) return;       // K half only produces the fp32 output
    const float* src = (kv ? g_vscr : g_kscr) + (size_t)b * CHW_;
    const int p0 = blockIdx.x << 5, i0 = blockIdx.y << 5;
    const int tx = threadIdx.x, ty = threadIdx.y;
    #pragma unroll
    for (int r = 0; r < 4; r++) {
        const int ii = ty + r * 8;
        tile[ii][tx] = src[(size_t)(2 * (i0 + ii) + par) * HW_ + p0 + tx];
    }
    __syncthreads();
    const size_t bofs = (size_t)b * CHW_;
    #pragma unroll
    for (int r = 0; r < 4; r++) {
        const int pp = ty + r * 8;
        const size_t idx = (size_t)(par * 16384 + p0 + pp) * 128 + i0 + tx;
        const float v = tile[tx][pp];
        if (dstf) dstf[bofs + idx] = v;
        if (kv) {
            __nv_bfloat16 h = __float2bfloat16_rn(v);
            g_vth[bofs + idx] = h;
            g_vtl[bofs + idx] = __float2bfloat16_rn(v - __bfloat162float(h));
        }
    }
}

// ---------------- kernel 3: split-K logit GEMM -------------------------------
// grid (SPLITK_, 8). A = Q planes, B = K planes (both natural layout).
__global__ __launch_bounds__(256, 2) void att_gemm_kernel()
{
    __shared__ __align__(16) uint32_t smb[12288];
    const int s = blockIdx.x, b = blockIdx.y;
    const size_t base = (size_t)b * (CHW_ / 2) + (size_t)(s >> 6) * 8192
                      + (size_t)(s & 63) * 128;

    HACC_INIT(acc);
    hmma_core((const char*)(g_qh + base), (const char*)(g_ql + base), 65536,
              (const char*)(g_kh + base), (const char*)(g_kl + base), 65536,
              16, acc, smb);

    float* Cp = g_psum + ((size_t)b * SPLITK_ + s) * 16384;
    const int lane = threadIdx.x & 31, w = threadIdx.x >> 5;
    const int g = lane >> 2, t4 = lane & 3, wm = w & 3, wn = w >> 2;
    #pragma unroll
    for (int im = 0; im < 2; im++) {
        const int mb = wm * 32 + im * 16;
        #pragma unroll
        for (int jn = 0; jn < 8; jn++) {
            const int n = wn * 64 + jn * 8 + t4 * 2;
            *(float2*)(Cp + (size_t)(mb + g    ) * 128 + n) =
                make_float2(acc[im][jn][0], acc[im][jn][1]);
            *(float2*)(Cp + (size_t)(mb + g + 8) * 128 + n) =
                make_float2(acc[im][jn][2], acc[im][jn][3]);
        }
    }
}

// ---------------- kernel 4: Kahan reduce + softmax (+ att bf16 planes) -------
// grid (128, 8): x = j' column, y = batch; 128 threads = i row
__global__ void softmax_kernel(float* __restrict__ attw,
                               float* __restrict__ gmw,
                               const float* __restrict__ gamma)
{
    const int b = blockIdx.y, ip = blockIdx.x, i = threadIdx.x;
    const float* base = g_psum + (size_t)b * SPLITK_ * 16384 + (size_t)i * 128 + ip;
    float s = 0.f, comp = 0.f;
    for (int t = 0; t < SPLITK_; t++) {
        float y = __fsub_rn(base[(size_t)t * 16384], comp);
        float u = __fadd_rn(s, y);
        comp = __fsub_rn(__fsub_rn(u, s), y);
        s = u;
    }
    __shared__ float red[128];
    red[i] = s;
    __syncthreads();
    for (int off = 64; off > 0; off >>= 1) {
        if (i < off) red[i] = fmaxf(red[i], red[i + off]);
        __syncthreads();
    }
    const float mx = red[0];
    __syncthreads();
    const float e = expf(s - mx);
    red[i] = e;
    __syncthreads();
    for (int off = 64; off > 0; off >>= 1) {
        if (i < off) red[i] += red[i + off];
        __syncthreads();
    }
    const float r = e / red[0];
    __nv_bfloat16 h = __float2bfloat16_rn(r);
    g_ath[(size_t)b * 16384 + (size_t)ip * 128 + i] = h;   // transposed [j'][i]
    g_atl[(size_t)b * 16384 + (size_t)ip * 128 + i] =
        __float2bfloat16_rn(r - __bfloat162float(h));
    if (attw) attw[(size_t)b * 16384 + (size_t)i * 128 + ip] = r;
    if (gmw && b == 0 && ip == 0 && i == 0) *gmw = __ldg(gamma);
}

// ---------------- kernel 5: out = Vt @ att, scaled by gamma ------------------
// grid (256, 8). A = Vt planes [j][i], B = att planes [j'][i].
__global__ __launch_bounds__(256, 2) void out_gemm_kernel(
    float* __restrict__ outw, const float* __restrict__ gamma)
{
    __shared__ __align__(16) uint32_t smb[12288];
    const int b  = blockIdx.y;
    const int m0 = blockIdx.x << 7;
    const char* Ah = (const char*)(g_vth + (size_t)b * CHW_ + (size_t)m0 * 128);
    const char* Al = (const char*)(g_vtl + (size_t)b * CHW_ + (size_t)m0 * 128);
    const char* Bh = (const char*)(g_ath + (size_t)b * 16384);
    const char* Bl = (const char*)(g_atl + (size_t)b * 16384);

    HACC_INIT(acc);
    hmma_core(Ah, Al, 256, Bh, Bl, 256, 8, acc, smb);

    const float gsc = __ldg(gamma);
    float* base = outw + (size_t)b * CHW_;
    const int lane = threadIdx.x & 31, w = threadIdx.x >> 5;
    const int g = lane >> 2, t4 = lane & 3, wm = w & 3, wn = w >> 2;
    #pragma unroll
    for (int im = 0; im < 2; im++) {
        const int mb = m0 + wm * 32 + im * 16;
        #pragma unroll
        for (int jn = 0; jn < 8; jn++) {
            const int n = wn * 64 + jn * 8 + t4 * 2;
            *(float2*)(base + (size_t)(mb + g    ) * 128 + n) =
                make_float2(acc[im][jn][0] * gsc, acc[im][jn][1] * gsc);
            *(float2*)(base + (size_t)(mb + g + 8) * 128 + n) =
                make_float2(acc[im][jn][2] * gsc, acc[im][jn][3] * gsc);
        }
    }
}

// ---------------- launch -----------------------------------------------------
extern "C" void kernel_launch(void* const* d_in, const int* in_sizes, int n_in,
                              void* d_out, int out_size)
{
    const float* x  = (const float*)d_in[0];
    const float* Wq = (const float*)d_in[1];
    const float* bq = (const float*)d_in[2];
    const float* Wk = (const float*)d_in[3];
    const float* bk = (const float*)d_in[4];
    const float* Wv = (const float*)d_in[5];
    const float* bv = (const float*)d_in[6];
    const float* gm = (const float*)d_in[7];
    float* out = (float*)d_out;

    const bool full = (out_size >= FULL_SIZE);
    float* outw = out;
    float* qw   = full ? out + OFF_QW    : nullptr;
    float* ktw  = full ? out + OFF_KW    : nullptr;
    float* vtw  = full ? out + OFF_VW    : nullptr;
    float* gmw  = full ? out + OFF_GAMMA : nullptr;
    float* attw = full ? out + OFF_ATT   : nullptr;

    wsplit_kernel<<<384, 256>>>(Wq, Wk, Wv);
    xsplit_kernel<<<dim3(512, 4, 8), dim3(32, 8)>>>(x);
    conv_qkv_kernel<<<dim3(128, 6, 8), 256>>>(bq, bk, bv, qw);
    transpose_kv_kernel<<<dim3(512, 4, 32), dim3(32, 8)>>>(ktw, vtw);
    att_gemm_kernel<<<dim3(SPLITK_, 8), 256>>>();
    softmax_kernel<<<dim3(128, 8), 128>>>(attw, gmw, gm);
    out_gemm_kernel<<<dim3(256, 8), 256>>>(outw, gm);
}